// round 4
// baseline (speedup 1.0000x reference)
#include <cuda_runtime.h>
#include <math_constants.h>

// Problem constants
#define B_   4
#define CIN  256
#define LAT  256
#define NPIX 4096   // 64*64

// SGEMM tiling
#define BM 128
#define BN 128
#define BK 8

// Scratch (allocation-free rule: __device__ globals)
__device__ __align__(16) float g_q[B_ * LAT * NPIX];
__device__ __align__(16) float g_k[B_ * LAT * NPIX];
__device__ __align__(16) float g_v[B_ * LAT * NPIX];
__device__ __align__(16) float g_T[(size_t)B_ * NPIX * NPIX];  // 256 MB logits (transposed: [j][i])
__device__ __align__(16) float g_r[B_ * NPIX * LAT];           // res^T: [j][c]

// Generic batched SGEMM: C[m,n] = alpha * sum_k Aelem(m,k)*Belem(k,n) (+ bias[m])
//   TA==0: A stored [M,K] row-major.  TA==1: A stored [K,M] (leading dim M).
//   TB==0: B stored [K,N].            TB==1: B stored [N,K] (leading dim K).
// All of M,N divisible by 128; K divisible by 8. No bounds checks needed.
template<int TA, int TB, bool BIAS>
__global__ __launch_bounds__(256, 2)
void sgemm(const float* __restrict__ A, size_t sA,
           const float* __restrict__ B, size_t sB,
           float* __restrict__ C, size_t sC,
           const float* __restrict__ bias,
           int M, int N, int K, float alpha)
{
    __shared__ float As[BK][BM];
    __shared__ float Bs[BK][BN];

    const int bz = blockIdx.z;
    A += (size_t)bz * sA;
    B += (size_t)bz * sB;
    C += (size_t)bz * sC;

    const int m0  = blockIdx.y * BM;
    const int n0  = blockIdx.x * BN;
    const int tid = threadIdx.x;
    const int tx  = tid & 15;   // 0..15
    const int ty  = tid >> 4;   // 0..15

    float acc[8][8];
#pragma unroll
    for (int i = 0; i < 8; i++)
#pragma unroll
        for (int j = 0; j < 8; j++) acc[i][j] = 0.f;

    for (int k0 = 0; k0 < K; k0 += BK) {
        // ---- load A tile into As[kk][mm] ----
        if (TA == 0) {
            const int row = tid >> 1;          // 0..127
            const int kc  = (tid & 1) * 4;     // 0 or 4
            float4 a = *(const float4*)(A + (size_t)(m0 + row) * K + (k0 + kc));
            As[kc + 0][row] = a.x;
            As[kc + 1][row] = a.y;
            As[kc + 2][row] = a.z;
            As[kc + 3][row] = a.w;
        } else {
            const int kk = tid >> 5;           // 0..7
            const int mm = (tid & 31) * 4;     // 0..124
            *(float4*)(&As[kk][mm]) =
                *(const float4*)(A + (size_t)(k0 + kk) * M + (m0 + mm));
        }
        // ---- load B tile into Bs[kk][nn] ----
        if (TB == 0) {
            const int kk = tid >> 5;
            const int nn = (tid & 31) * 4;
            *(float4*)(&Bs[kk][nn]) =
                *(const float4*)(B + (size_t)(k0 + kk) * N + (n0 + nn));
        } else {
            const int row = tid >> 1;
            const int kc  = (tid & 1) * 4;
            float4 b = *(const float4*)(B + (size_t)(n0 + row) * K + (k0 + kc));
            Bs[kc + 0][row] = b.x;
            Bs[kc + 1][row] = b.y;
            Bs[kc + 2][row] = b.z;
            Bs[kc + 3][row] = b.w;
        }
        __syncthreads();

#pragma unroll
        for (int kk = 0; kk < BK; kk++) {
            float ra[8], rb[8];
            *(float4*)&ra[0] = *(const float4*)&As[kk][ty * 4];
            *(float4*)&ra[4] = *(const float4*)&As[kk][64 + ty * 4];
            *(float4*)&rb[0] = *(const float4*)&Bs[kk][tx * 4];
            *(float4*)&rb[4] = *(const float4*)&Bs[kk][64 + tx * 4];
#pragma unroll
            for (int i = 0; i < 8; i++)
#pragma unroll
                for (int j = 0; j < 8; j++)
                    acc[i][j] = fmaf(ra[i], rb[j], acc[i][j]);
        }
        __syncthreads();
    }

    // ---- epilogue ----
#pragma unroll
    for (int i = 0; i < 8; i++) {
        const int row = m0 + ((i < 4) ? (ty * 4 + i) : (64 + ty * 4 + (i - 4)));
        const float bv = BIAS ? bias[row] : 0.f;
#pragma unroll
        for (int jv = 0; jv < 2; jv++) {
            const int col = n0 + ((jv == 0) ? (tx * 4) : (64 + tx * 4));
            float4 o;
            o.x = alpha * acc[i][jv * 4 + 0] + bv;
            o.y = alpha * acc[i][jv * 4 + 1] + bv;
            o.z = alpha * acc[i][jv * 4 + 2] + bv;
            o.w = alpha * acc[i][jv * 4 + 3] + bv;
            *(float4*)(C + (size_t)row * N + col) = o;
        }
    }
}

// Row-wise softmax over NPIX contiguous values (one CTA per row, in place).
__global__ __launch_bounds__(256)
void softmax_rows(float* __restrict__ T)
{
    float* row = T + (size_t)blockIdx.x * NPIX;
    const int tid  = threadIdx.x;
    const int lane = tid & 31;
    const int wid  = tid >> 5;

    float v[16];
    float m = -CUDART_INF_F;
#pragma unroll
    for (int t = 0; t < 16; t++) {
        v[t] = row[tid + t * 256];
        m = fmaxf(m, v[t]);
    }
#pragma unroll
    for (int o = 16; o > 0; o >>= 1)
        m = fmaxf(m, __shfl_xor_sync(0xffffffffu, m, o));

    __shared__ float rmax[8];
    __shared__ float rsum[8];
    if (lane == 0) rmax[wid] = m;
    __syncthreads();
#pragma unroll
    for (int w = 0; w < 8; w++) m = fmaxf(m, rmax[w]);

    float s = 0.f;
#pragma unroll
    for (int t = 0; t < 16; t++) {
        v[t] = __expf(v[t] - m);
        s += v[t];
    }
#pragma unroll
    for (int o = 16; o > 0; o >>= 1)
        s += __shfl_xor_sync(0xffffffffu, s, o);
    if (lane == 0) rsum[wid] = s;
    __syncthreads();
    float tot = 0.f;
#pragma unroll
    for (int w = 0; w < 8; w++) tot += rsum[w];
    const float inv = 1.f / tot;

#pragma unroll
    for (int t = 0; t < 16; t++)
        row[tid + t * 256] = v[t] * inv;
}

extern "C" void kernel_launch(void* const* d_in, const int* in_sizes, int n_in,
                              void* d_out, int out_size)
{
    (void)in_sizes; (void)n_in; (void)out_size;
    const float* x  = (const float*)d_in[0];
    const float* Wq = (const float*)d_in[1];
    const float* bq = (const float*)d_in[2];
    const float* Wk = (const float*)d_in[3];
    const float* bk = (const float*)d_in[4];
    const float* Wv = (const float*)d_in[5];
    const float* bv = (const float*)d_in[6];
    const float* Wo = (const float*)d_in[7];
    const float* bo = (const float*)d_in[8];
    float* out = (float*)d_out;

    float *q, *k, *v, *T, *r;
    cudaGetSymbolAddress((void**)&q, g_q);
    cudaGetSymbolAddress((void**)&k, g_k);
    cudaGetSymbolAddress((void**)&v, g_v);
    cudaGetSymbolAddress((void**)&T, g_T);
    cudaGetSymbolAddress((void**)&r, g_r);

    const size_t sQ = (size_t)LAT * NPIX;
    const size_t sX = (size_t)CIN * NPIX;
    const size_t sT = (size_t)NPIX * NPIX;
    const size_t sR = (size_t)NPIX * LAT;

    dim3 blk(256);

    // 1) q/k/v[b] = W @ x[b] + bias      (A:[M,K] NN, B:[K,N])  M=256,N=4096,K=256
    dim3 g1(NPIX / BN, LAT / BM, B_);
    sgemm<0, 0, true><<<g1, blk>>>(Wq, 0, x, sX, q, sQ, bq, LAT, NPIX, CIN, 1.f);
    sgemm<0, 0, true><<<g1, blk>>>(Wk, 0, x, sX, k, sQ, bk, LAT, NPIX, CIN, 1.f);
    sgemm<0, 0, true><<<g1, blk>>>(Wv, 0, x, sX, v, sQ, bv, LAT, NPIX, CIN, 1.f);

    // 2) T[b][j][i] = (k_j . q_i) / 16   (A=k [K,M] TN, B=q [K,N])  M=N=4096,K=256
    dim3 g2(NPIX / BN, NPIX / BM, B_);
    sgemm<1, 0, false><<<g2, blk>>>(k, sQ, q, sQ, T, sT, nullptr,
                                    NPIX, NPIX, LAT, 1.f / 16.f);

    // 3) softmax over i (contiguous) per (b, j) row
    softmax_rows<<<B_ * NPIX, 256>>>(T);

    // 4) r[b][j][c] = sum_i T[j][i] * v[c][i]   (A=T NN, B=v [N,K] NT)  M=4096,N=256,K=4096
    dim3 g3(LAT / BN, NPIX / BM, B_);
    sgemm<0, 1, false><<<g3, blk>>>(T, sT, v, sQ, r, sR, nullptr,
                                    NPIX, LAT, NPIX, 1.f);

    // 5) out[b][o][j] = Wo @ r^T + bo    (A=Wo NN, B=r [N,K] NT)  M=256,N=4096,K=256
    dim3 g4(NPIX / BN, CIN / BM, B_);
    sgemm<0, 1, true><<<g4, blk>>>(Wo, 0, r, sR, out, sX, bo,
                                   CIN, NPIX, LAT, 1.f);
}

// round 8
// speedup vs baseline: 1.3793x; 1.3793x over previous
#include <cuda_runtime.h>
#include <cuda_bf16.h>
#include <math_constants.h>

#define B_   4
#define CIN  256
#define LAT  256
#define NPIX 4096   // 64*64

// ---------------- scratch (__device__ globals; no allocs allowed) ----------------
__device__ __align__(16) __nv_bfloat16 g_xT_hi[B_ * NPIX * CIN];   // x^T  [b][n][c]
__device__ __align__(16) __nv_bfloat16 g_xT_lo[B_ * NPIX * CIN];
__device__ __align__(16) __nv_bfloat16 g_w_hi[4 * LAT * CIN];      // Wq,Wk,Wv,Wo
__device__ __align__(16) __nv_bfloat16 g_w_lo[4 * LAT * CIN];
__device__ __align__(16) __nv_bfloat16 g_q_hi[B_ * NPIX * LAT];    // q^T [b][n][l]
__device__ __align__(16) __nv_bfloat16 g_q_lo[B_ * NPIX * LAT];
__device__ __align__(16) __nv_bfloat16 g_k_hi[B_ * NPIX * LAT];    // k^T
__device__ __align__(16) __nv_bfloat16 g_k_lo[B_ * NPIX * LAT];
__device__ __align__(16) __nv_bfloat16 g_v_hi[B_ * LAT * NPIX];    // v   [b][l][n]
__device__ __align__(16) __nv_bfloat16 g_v_lo[B_ * LAT * NPIX];
__device__ __align__(16) float         g_T[(size_t)B_ * NPIX * NPIX];   // logits [b][j][i] f32
__device__ __align__(16) __nv_bfloat16 g_P_hi[(size_t)B_ * NPIX * NPIX];
__device__ __align__(16) __nv_bfloat16 g_P_lo[(size_t)B_ * NPIX * NPIX];
__device__ __align__(16) __nv_bfloat16 g_r_hi[B_ * NPIX * LAT];    // r [b][j][c]
__device__ __align__(16) __nv_bfloat16 g_r_lo[B_ * NPIX * LAT];

// ---------------- helpers ----------------
__device__ __forceinline__ unsigned s2u(const void* p) {
    unsigned a;
    asm("{ .reg .u64 t; cvta.to.shared.u64 t, %1; cvt.u32.u64 %0, t; }" : "=r"(a) : "l"(p));
    return a;
}
__device__ __forceinline__ void cp16(unsigned s, const void* g) {
    asm volatile("cp.async.cg.shared.global [%0], [%1], 16;" :: "r"(s), "l"(g));
}
#define CP_COMMIT() asm volatile("cp.async.commit_group;" ::: "memory")
#define CP_WAIT1()  asm volatile("cp.async.wait_group 1;" ::: "memory")
#define CP_WAIT0()  asm volatile("cp.async.wait_group 0;" ::: "memory")

__device__ __forceinline__ void ldm_x4(unsigned& r0, unsigned& r1, unsigned& r2, unsigned& r3,
                                       unsigned addr) {
    asm volatile("ldmatrix.sync.aligned.m8n8.x4.shared.b16 {%0,%1,%2,%3}, [%4];"
                 : "=r"(r0), "=r"(r1), "=r"(r2), "=r"(r3) : "r"(addr));
}
__device__ __forceinline__ void mma_bf16(float* c, const unsigned* a, const unsigned* b) {
    asm volatile(
        "mma.sync.aligned.m16n8k16.row.col.f32.bf16.bf16.f32 "
        "{%0,%1,%2,%3}, {%4,%5,%6,%7}, {%8,%9}, {%0,%1,%2,%3};"
        : "+f"(c[0]), "+f"(c[1]), "+f"(c[2]), "+f"(c[3])
        : "r"(a[0]), "r"(a[1]), "r"(a[2]), "r"(a[3]), "r"(b[0]), "r"(b[1]));
}

// ---------------- HMMA GEMM: D[m,n] = sum_k A[m,k]*B[n,k], bf16 hi/lo split ----------------
// A_hi/A_lo: [M][K] bf16 (row stride K).  B_hi/B_lo: [N][K] bf16.
// Accumulates 3 segments: hi*hi + lo*hi + hi*lo into f32 register accumulators.
// EPI: 0 = f32 * alpha          (logits)
//      1 = f32 + bias[row]      (final out)
//      2 = split + bias[col]    (q, k projections)
//      3 = split + bias[row]    (v projection)
//      4 = split, no bias       (r)
// CTA tile 128x128, BK=64 (bf16), 8 warps (2x4), warp tile 64x32.
#define SMEM_GEMM_BYTES 65536
template<int EPI>
__global__ __launch_bounds__(256, 2)
void tc_gemm(const __nv_bfloat16* __restrict__ A_hi, const __nv_bfloat16* __restrict__ A_lo, size_t sA,
             const __nv_bfloat16* __restrict__ B_hi, const __nv_bfloat16* __restrict__ B_lo, size_t sB,
             float* __restrict__ Cf, __nv_bfloat16* __restrict__ Ch, __nv_bfloat16* __restrict__ Cl,
             size_t sC, const float* __restrict__ bias, int N, int K, float alpha)
{
    extern __shared__ char smem[];
    const unsigned sbase = s2u(smem);
    const int tid  = threadIdx.x;
    const int warp = tid >> 5, lane = tid & 31;
    const int wm   = (warp >> 2) * 64;      // warp m offset in CTA tile
    const int wn   = (warp & 3) * 32;       // warp n offset
    const int m0   = blockIdx.y * 128, n0 = blockIdx.x * 128, bz = blockIdx.z;

    A_hi += (size_t)bz * sA;  A_lo += (size_t)bz * sA;
    B_hi += (size_t)bz * sB;  B_lo += (size_t)bz * sB;

    const int KC = K >> 6;       // 64-wide K chunks per segment
    const int T  = 3 * KC;       // segments: hi*hi, lo*hi, hi*lo

    // stage loader: 256 threads, threads 0..127 -> A rows, 128..255 -> B rows.
    // SW128 swizzle: smem_off(row,c16) = row*128 + (c16*16 ^ ((row&7)<<4))
    auto load_st = [&](int st) {
        const int buf = st & 1;
        const int seg = st / KC;
        const int kc  = st - seg * KC;
        const int r   = tid & 127;
        const __nv_bfloat16* src;
        unsigned sa;
        if (tid < 128) {
            src = (seg == 1 ? A_lo : A_hi) + (size_t)(m0 + r) * K + (kc << 6);
            sa  = sbase + buf * 32768u;
        } else {
            src = (seg == 2 ? B_lo : B_hi) + (size_t)(n0 + r) * K + (kc << 6);
            sa  = sbase + buf * 32768u + 16384u;
        }
        const unsigned pat  = (unsigned)(r & 7) << 4;
        const unsigned base = sa + (unsigned)r * 128u;
#pragma unroll
        for (int c = 0; c < 8; c++)
            cp16(base + (((unsigned)c * 16u) ^ pat), src + c * 8);
        CP_COMMIT();
    };

    float acc[4][4][4];
#pragma unroll
    for (int i = 0; i < 4; i++)
#pragma unroll
        for (int j = 0; j < 4; j++)
#pragma unroll
            for (int e = 0; e < 4; e++) acc[i][j][e] = 0.f;

    load_st(0);
    load_st(1);

    const unsigned lpat = (unsigned)(lane & 7) << 4;   // swizzle XOR pattern for ldmatrix

    for (int st = 0; st < T; st++) {
        if (st + 1 < T) CP_WAIT1(); else CP_WAIT0();
        __syncthreads();

        const unsigned abase = sbase + (unsigned)(st & 1) * 32768u;
        const unsigned bbase = abase + 16384u;

#pragma unroll
        for (int k16 = 0; k16 < 4; k16++) {
            unsigned a[4][4], b[4][2];
            // A fragments: 4 x (m16 x k16), lines = m-rows
#pragma unroll
            for (int fm = 0; fm < 4; fm++) {
                const unsigned mrow = (unsigned)(wm + fm * 16 + (lane & 7) + ((lane >> 3) & 1) * 8);
                const unsigned kb   = (unsigned)(k16 * 32 + ((lane >> 4) & 1) * 16);
                ldm_x4(a[fm][0], a[fm][1], a[fm][2], a[fm][3],
                       abase + mrow * 128u + (kb ^ lpat));
            }
            // B fragments: 4 x (k16 x n8), lines = n-rows; one x4 covers two n8 frags
#pragma unroll
            for (int p = 0; p < 2; p++) {
                const unsigned grp  = (unsigned)(lane >> 3);
                const unsigned nrow = (unsigned)(wn + p * 16 + (lane & 7)) + (grp >> 1) * 8u;
                const unsigned kb   = (unsigned)k16 * 32u + (grp & 1) * 16u;
                unsigned r0, r1, r2, r3;
                ldm_x4(r0, r1, r2, r3, bbase + nrow * 128u + (kb ^ lpat));
                b[p * 2][0] = r0;  b[p * 2][1] = r1;
                b[p * 2 + 1][0] = r2;  b[p * 2 + 1][1] = r3;
            }
#pragma unroll
            for (int fm = 0; fm < 4; fm++)
#pragma unroll
                for (int fn = 0; fn < 4; fn++)
                    mma_bf16(acc[fm][fn], a[fm], b[fn]);
        }
        __syncthreads();
        if (st + 2 < T) load_st(st + 2);
    }

    // ---- epilogue: acc[fm][fn] is m16n8 at (wm+fm*16, wn+fn*8) ----
    const int g  = lane >> 2;    // row within frag (and +8)
    const int tc = lane & 3;     // col pair index
#pragma unroll
    for (int fm = 0; fm < 4; fm++) {
        const int r0 = m0 + wm + fm * 16 + g;
        const int r1 = r0 + 8;
        float b0 = 0.f, b1 = 0.f;
        if (EPI == 1 || EPI == 3) { b0 = bias[r0]; b1 = bias[r1]; }
#pragma unroll
        for (int fn = 0; fn < 4; fn++) {
            const int col = n0 + wn + fn * 8 + tc * 2;
            float v00 = acc[fm][fn][0], v01 = acc[fm][fn][1];   // row r0
            float v10 = acc[fm][fn][2], v11 = acc[fm][fn][3];   // row r1
            if (EPI == 0) { v00 *= alpha; v01 *= alpha; v10 *= alpha; v11 *= alpha; }
            if (EPI == 1 || EPI == 3) { v00 += b0; v01 += b0; v10 += b1; v11 += b1; }
            if (EPI == 2) {
                const float bc0 = bias[col], bc1 = bias[col + 1];
                v00 += bc0; v01 += bc1; v10 += bc0; v11 += bc1;
            }
            if (EPI == 0 || EPI == 1) {
                float* o0 = Cf + (size_t)bz * sC + (size_t)r0 * N + col;
                float* o1 = Cf + (size_t)bz * sC + (size_t)r1 * N + col;
                *(float2*)o0 = make_float2(v00, v01);
                *(float2*)o1 = make_float2(v10, v11);
            } else {
                __nv_bfloat16 h00 = __float2bfloat16(v00), h01 = __float2bfloat16(v01);
                __nv_bfloat16 h10 = __float2bfloat16(v10), h11 = __float2bfloat16(v11);
                __nv_bfloat162 hh0; hh0.x = h00; hh0.y = h01;
                __nv_bfloat162 hh1; hh1.x = h10; hh1.y = h11;
                __nv_bfloat162 ll0, ll1;
                ll0.x = __float2bfloat16(v00 - __bfloat162float(h00));
                ll0.y = __float2bfloat16(v01 - __bfloat162float(h01));
                ll1.x = __float2bfloat16(v10 - __bfloat162float(h10));
                ll1.y = __float2bfloat16(v11 - __bfloat162float(h11));
                __nv_bfloat16* c0 = Ch + (size_t)bz * sC + (size_t)r0 * N + col;
                __nv_bfloat16* c1 = Ch + (size_t)bz * sC + (size_t)r1 * N + col;
                __nv_bfloat16* d0 = Cl + (size_t)bz * sC + (size_t)r0 * N + col;
                __nv_bfloat16* d1 = Cl + (size_t)bz * sC + (size_t)r1 * N + col;
                *(__nv_bfloat162*)c0 = hh0;
                *(__nv_bfloat162*)c1 = hh1;
                *(__nv_bfloat162*)d0 = ll0;
                *(__nv_bfloat162*)d1 = ll1;
            }
        }
    }
}

// ---------------- transpose + split: x[b][c][n] f32 -> xT hi/lo [b][n][c] ----------------
__global__ __launch_bounds__(256)
void xT_split(const float* __restrict__ x, __nv_bfloat16* __restrict__ th,
              __nv_bfloat16* __restrict__ tl)
{
    __shared__ float t[32][33];
    const int b = blockIdx.z;
    const int n0 = blockIdx.x * 32, c0 = blockIdx.y * 32;
    const int tx = threadIdx.x, ty = threadIdx.y;    // (32, 8)
    const float* xb = x + (size_t)b * CIN * NPIX;
#pragma unroll
    for (int j = 0; j < 4; j++)
        t[ty + j * 8][tx] = xb[(size_t)(c0 + ty + j * 8) * NPIX + n0 + tx];
    __syncthreads();
#pragma unroll
    for (int j = 0; j < 4; j++) {
        float v = t[tx][ty + j * 8];
        __nv_bfloat16 hh = __float2bfloat16(v);
        size_t o = ((size_t)b * NPIX + n0 + ty + j * 8) * CIN + c0 + tx;
        th[o] = hh;
        tl[o] = __float2bfloat16(v - __bfloat162float(hh));
    }
}

// ---------------- elementwise split (weights) ----------------
__global__ __launch_bounds__(256)
void split_f32(const float* __restrict__ s, __nv_bfloat16* __restrict__ h,
               __nv_bfloat16* __restrict__ l, int n)
{
    int i = blockIdx.x * 256 + threadIdx.x;
    if (i < n) {
        float v = s[i];
        __nv_bfloat16 hh = __float2bfloat16(v);
        h[i] = hh;
        l[i] = __float2bfloat16(v - __bfloat162float(hh));
    }
}

// ---------------- softmax over contiguous NPIX + split to bf16 hi/lo ----------------
__global__ __launch_bounds__(256)
void softmax_split(const float* __restrict__ T, __nv_bfloat16* __restrict__ Ph,
                   __nv_bfloat16* __restrict__ Pl)
{
    const float* row = T + (size_t)blockIdx.x * NPIX;
    const int tid = threadIdx.x, lane = tid & 31, wid = tid >> 5;

    float v[16];
    float m = -CUDART_INF_F;
#pragma unroll
    for (int t = 0; t < 16; t++) { v[t] = row[tid + t * 256]; m = fmaxf(m, v[t]); }
#pragma unroll
    for (int o = 16; o > 0; o >>= 1) m = fmaxf(m, __shfl_xor_sync(0xffffffffu, m, o));

    __shared__ float rmax[8], rsum[8];
    if (lane == 0) rmax[wid] = m;
    __syncthreads();
#pragma unroll
    for (int w = 0; w < 8; w++) m = fmaxf(m, rmax[w]);

    float s = 0.f;
#pragma unroll
    for (int t = 0; t < 16; t++) { v[t] = __expf(v[t] - m); s += v[t]; }
#pragma unroll
    for (int o = 16; o > 0; o >>= 1) s += __shfl_xor_sync(0xffffffffu, s, o);
    if (lane == 0) rsum[wid] = s;
    __syncthreads();
    float tot = 0.f;
#pragma unroll
    for (int w = 0; w < 8; w++) tot += rsum[w];
    const float inv = 1.f / tot;

    const size_t o = (size_t)blockIdx.x * NPIX;
#pragma unroll
    for (int t = 0; t < 16; t++) {
        float p = v[t] * inv;
        __nv_bfloat16 hh = __float2bfloat16(p);
        Ph[o + tid + t * 256] = hh;
        Pl[o + tid + t * 256] = __float2bfloat16(p - __bfloat162float(hh));
    }
}

// ---------------- launch ----------------
extern "C" void kernel_launch(void* const* d_in, const int* in_sizes, int n_in,
                              void* d_out, int out_size)
{
    (void)in_sizes; (void)n_in; (void)out_size;
    const float* x  = (const float*)d_in[0];
    const float* Wq = (const float*)d_in[1];
    const float* bq = (const float*)d_in[2];
    const float* Wk = (const float*)d_in[3];
    const float* bk = (const float*)d_in[4];
    const float* Wv = (const float*)d_in[5];
    const float* bv = (const float*)d_in[6];
    const float* Wo = (const float*)d_in[7];
    const float* bo = (const float*)d_in[8];
    float* out = (float*)d_out;

    __nv_bfloat16 *xh, *xl, *wh, *wl, *qh, *ql, *kh, *kl, *vh, *vl, *Ph, *Pl, *rh, *rl;
    float* Tf;
    cudaGetSymbolAddress((void**)&xh, g_xT_hi);  cudaGetSymbolAddress((void**)&xl, g_xT_lo);
    cudaGetSymbolAddress((void**)&wh, g_w_hi);   cudaGetSymbolAddress((void**)&wl, g_w_lo);
    cudaGetSymbolAddress((void**)&qh, g_q_hi);   cudaGetSymbolAddress((void**)&ql, g_q_lo);
    cudaGetSymbolAddress((void**)&kh, g_k_hi);   cudaGetSymbolAddress((void**)&kl, g_k_lo);
    cudaGetSymbolAddress((void**)&vh, g_v_hi);   cudaGetSymbolAddress((void**)&vl, g_v_lo);
    cudaGetSymbolAddress((void**)&Tf, g_T);
    cudaGetSymbolAddress((void**)&Ph, g_P_hi);   cudaGetSymbolAddress((void**)&Pl, g_P_lo);
    cudaGetSymbolAddress((void**)&rh, g_r_hi);   cudaGetSymbolAddress((void**)&rl, g_r_lo);

    cudaFuncSetAttribute(tc_gemm<0>, cudaFuncAttributeMaxDynamicSharedMemorySize, SMEM_GEMM_BYTES);
    cudaFuncSetAttribute(tc_gemm<1>, cudaFuncAttributeMaxDynamicSharedMemorySize, SMEM_GEMM_BYTES);
    cudaFuncSetAttribute(tc_gemm<2>, cudaFuncAttributeMaxDynamicSharedMemorySize, SMEM_GEMM_BYTES);
    cudaFuncSetAttribute(tc_gemm<3>, cudaFuncAttributeMaxDynamicSharedMemorySize, SMEM_GEMM_BYTES);
    cudaFuncSetAttribute(tc_gemm<4>, cudaFuncAttributeMaxDynamicSharedMemorySize, SMEM_GEMM_BYTES);

    const size_t sX = (size_t)NPIX * CIN;   // x^T per-batch stride (elems)
    const size_t sQ = (size_t)NPIX * LAT;   // q^T / k^T / r per-batch stride
    const size_t sV = (size_t)LAT * NPIX;   // v per-batch stride
    const size_t sT = (size_t)NPIX * NPIX;  // logits / P per-batch stride
    const int    WN = LAT * CIN;            // 65536

    // 0) conversions
    xT_split<<<dim3(NPIX / 32, CIN / 32, B_), dim3(32, 8)>>>(x, xh, xl);
    split_f32<<<WN / 256, 256>>>(Wq, wh + 0 * WN, wl + 0 * WN, WN);
    split_f32<<<WN / 256, 256>>>(Wk, wh + 1 * WN, wl + 1 * WN, WN);
    split_f32<<<WN / 256, 256>>>(Wv, wh + 2 * WN, wl + 2 * WN, WN);
    split_f32<<<WN / 256, 256>>>(Wo, wh + 3 * WN, wl + 3 * WN, WN);

    // 1) q^T[n,l] = sum_c xT[n,c]*Wq[l,c] + bq[l]   (EPI 2: split, bias over col)
    tc_gemm<2><<<dim3(LAT / 128, NPIX / 128, B_), 256, SMEM_GEMM_BYTES>>>(
        xh, xl, sX, wh + 0 * WN, wl + 0 * WN, 0, nullptr, qh, ql, sQ, bq, LAT, CIN, 1.f);
    tc_gemm<2><<<dim3(LAT / 128, NPIX / 128, B_), 256, SMEM_GEMM_BYTES>>>(
        xh, xl, sX, wh + 1 * WN, wl + 1 * WN, 0, nullptr, kh, kl, sQ, bk, LAT, CIN, 1.f);
    // v[l,n] = sum_c Wv[l,c]*xT[n,c] + bv[l]        (EPI 3: split, bias over row)
    tc_gemm<3><<<dim3(NPIX / 128, LAT / 128, B_), 256, SMEM_GEMM_BYTES>>>(
        wh + 2 * WN, wl + 2 * WN, 0, xh, xl, sX, nullptr, vh, vl, sV, bv, NPIX, CIN, 1.f);

    // 2) T[j,i] = (sum_c kT[j,c]*qT[i,c]) / 16      (EPI 0: f32 * alpha)
    tc_gemm<0><<<dim3(NPIX / 128, NPIX / 128, B_), 256, SMEM_GEMM_BYTES>>>(
        kh, kl, sQ, qh, ql, sQ, Tf, nullptr, nullptr, sT, nullptr, NPIX, LAT, 1.f / 16.f);

    // 3) softmax over i (contiguous) per (b, j) row; emit P hi/lo
    softmax_split<<<B_ * NPIX, 256>>>(Tf, Ph, Pl);

    // 4) r[j,c] = sum_i P[j,i]*v[c,i]               (EPI 4: split, no bias)
    tc_gemm<4><<<dim3(LAT / 128, NPIX / 128, B_), 256, SMEM_GEMM_BYTES>>>(
        Ph, Pl, sT, vh, vl, sV, nullptr, rh, rl, sQ, nullptr, LAT, NPIX, 1.f);

    // 5) out[o,j] = sum_c Wo[o,c]*r[j,c] + bo[o]    (EPI 1: f32 + bias row)
    tc_gemm<1><<<dim3(NPIX / 128, CIN / 128, B_), 256, SMEM_GEMM_BYTES>>>(
        wh + 3 * WN, wl + 3 * WN, 0, rh, rl, sQ, out, nullptr, nullptr,
        (size_t)CIN * NPIX, bo, NPIX, LAT, 1.f);
}

// round 9
// speedup vs baseline: 1.9487x; 1.4129x over previous
#include <cuda_runtime.h>
#include <cuda_bf16.h>
#include <cuda_fp16.h>
#include <math_constants.h>

#define B_   4
#define CIN  256
#define LAT  256
#define NPIX 4096   // 64*64

// ---------------- scratch (__device__ globals; no allocs allowed) ----------------
__device__ __align__(16) __nv_bfloat16 g_xT_hi[B_ * NPIX * CIN];   // x^T  [b][n][c]
__device__ __align__(16) __nv_bfloat16 g_xT_lo[B_ * NPIX * CIN];
__device__ __align__(16) __nv_bfloat16 g_w_hi[4 * LAT * CIN];      // Wq,Wk,Wv,Wo
__device__ __align__(16) __nv_bfloat16 g_w_lo[4 * LAT * CIN];
__device__ __align__(16) __nv_bfloat16 g_q_hi[B_ * NPIX * LAT];    // q^T [b][n][l]
__device__ __align__(16) __nv_bfloat16 g_q_lo[B_ * NPIX * LAT];
__device__ __align__(16) __nv_bfloat16 g_k_hi[B_ * NPIX * LAT];    // k^T
__device__ __align__(16) __nv_bfloat16 g_k_lo[B_ * NPIX * LAT];
__device__ __align__(16) __half        g_v_h[B_ * LAT * NPIX];     // v fp16 [b][l][n]
__device__ __align__(16) float         g_T[(size_t)B_ * NPIX * NPIX];   // logits [b][j][i] f32
__device__ __align__(16) __half        g_P_h[(size_t)B_ * NPIX * NPIX]; // P fp16 [b][j][i]
__device__ __align__(16) __nv_bfloat16 g_r_hi[B_ * NPIX * LAT];    // r [b][j][c]
__device__ __align__(16) __nv_bfloat16 g_r_lo[B_ * NPIX * LAT];

// ---------------- helpers ----------------
__device__ __forceinline__ unsigned s2u(const void* p) {
    unsigned a;
    asm("{ .reg .u64 t; cvta.to.shared.u64 t, %1; cvt.u32.u64 %0, t; }" : "=r"(a) : "l"(p));
    return a;
}
__device__ __forceinline__ void cp16(unsigned s, const void* g) {
    asm volatile("cp.async.cg.shared.global [%0], [%1], 16;" :: "r"(s), "l"(g));
}
#define CP_COMMIT() asm volatile("cp.async.commit_group;" ::: "memory")
#define CP_WAIT1()  asm volatile("cp.async.wait_group 1;" ::: "memory")
#define CP_WAIT0()  asm volatile("cp.async.wait_group 0;" ::: "memory")

__device__ __forceinline__ void ldm_x4(unsigned& r0, unsigned& r1, unsigned& r2, unsigned& r3,
                                       unsigned addr) {
    asm volatile("ldmatrix.sync.aligned.m8n8.x4.shared.b16 {%0,%1,%2,%3}, [%4];"
                 : "=r"(r0), "=r"(r1), "=r"(r2), "=r"(r3) : "r"(addr));
}
__device__ __forceinline__ void mma_bf16(float* c, const unsigned* a, const unsigned* b) {
    asm volatile(
        "mma.sync.aligned.m16n8k16.row.col.f32.bf16.bf16.f32 "
        "{%0,%1,%2,%3}, {%4,%5,%6,%7}, {%8,%9}, {%0,%1,%2,%3};"
        : "+f"(c[0]), "+f"(c[1]), "+f"(c[2]), "+f"(c[3])
        : "r"(a[0]), "r"(a[1]), "r"(a[2]), "r"(a[3]), "r"(b[0]), "r"(b[1]));
}
__device__ __forceinline__ void mma_fp16(float* c, const unsigned* a, const unsigned* b) {
    asm volatile(
        "mma.sync.aligned.m16n8k16.row.col.f32.f16.f16.f32 "
        "{%0,%1,%2,%3}, {%4,%5,%6,%7}, {%8,%9}, {%0,%1,%2,%3};"
        : "+f"(c[0]), "+f"(c[1]), "+f"(c[2]), "+f"(c[3])
        : "r"(a[0]), "r"(a[1]), "r"(a[2]), "r"(a[3]), "r"(b[0]), "r"(b[1]));
}

// ---------------- HMMA GEMM: D[m,n] = sum_k A[m,k]*B[n,k] ----------------
// 16-bit element arrays (bf16 or fp16), K-major.
// NSEG==3: hi/lo bf16 split, accumulates hi*hi + lo*hi + hi*lo.
// NSEG==1: single-segment (A_lo/B_lo unused).
// EPI: 0 = f32 * alpha          (logits)
//      1 = f32 + bias[row]      (final out)
//      2 = split + bias[col]    (q, k projections)
//      4 = split, no bias       (r)
//      5 = fp16 + bias[row]     (v projection)
// CTA tile 128x128, BK=64, 8 warps (2x4), warp tile 64x32.
#define SMEM_GEMM_BYTES 65536
template<int EPI, int NSEG, bool FP16>
__global__ __launch_bounds__(256, 2)
void tc_gemm(const __nv_bfloat16* __restrict__ A_hi, const __nv_bfloat16* __restrict__ A_lo, size_t sA,
             const __nv_bfloat16* __restrict__ B_hi, const __nv_bfloat16* __restrict__ B_lo, size_t sB,
             float* __restrict__ Cf, __nv_bfloat16* __restrict__ Ch, __nv_bfloat16* __restrict__ Cl,
             size_t sC, const float* __restrict__ bias, int N, int K, float alpha)
{
    extern __shared__ char smem[];
    const unsigned sbase = s2u(smem);
    const int tid  = threadIdx.x;
    const int warp = tid >> 5, lane = tid & 31;
    const int wm   = (warp >> 2) * 64;      // warp m offset in CTA tile
    const int wn   = (warp & 3) * 32;       // warp n offset
    const int m0   = blockIdx.y * 128, n0 = blockIdx.x * 128, bz = blockIdx.z;

    A_hi += (size_t)bz * sA;  B_hi += (size_t)bz * sB;
    if (NSEG == 3) { A_lo += (size_t)bz * sA;  B_lo += (size_t)bz * sB; }

    const int KC = K >> 6;       // 64-wide K chunks per segment
    const int T  = NSEG * KC;

    auto load_st = [&](int st) {
        const int buf = st & 1;
        const int seg = (NSEG == 3) ? (st / KC) : 0;
        const int kc  = st - seg * KC;
        const int r   = tid & 127;
        const __nv_bfloat16* src;
        unsigned sa;
        if (tid < 128) {
            src = ((NSEG == 3 && seg == 1) ? A_lo : A_hi) + (size_t)(m0 + r) * K + (kc << 6);
            sa  = sbase + buf * 32768u;
        } else {
            src = ((NSEG == 3 && seg == 2) ? B_lo : B_hi) + (size_t)(n0 + r) * K + (kc << 6);
            sa  = sbase + buf * 32768u + 16384u;
        }
        const unsigned pat  = (unsigned)(r & 7) << 4;
        const unsigned base = sa + (unsigned)r * 128u;
#pragma unroll
        for (int c = 0; c < 8; c++)
            cp16(base + (((unsigned)c * 16u) ^ pat), src + c * 8);
        CP_COMMIT();
    };

    float acc[4][4][4];
#pragma unroll
    for (int i = 0; i < 4; i++)
#pragma unroll
        for (int j = 0; j < 4; j++)
#pragma unroll
            for (int e = 0; e < 4; e++) acc[i][j][e] = 0.f;

    load_st(0);
    load_st(1);

    const unsigned lpat = (unsigned)(lane & 7) << 4;

    for (int st = 0; st < T; st++) {
        if (st + 1 < T) CP_WAIT1(); else CP_WAIT0();
        __syncthreads();

        const unsigned abase = sbase + (unsigned)(st & 1) * 32768u;
        const unsigned bbase = abase + 16384u;

#pragma unroll
        for (int k16 = 0; k16 < 4; k16++) {
            unsigned a[4][4], b[4][2];
#pragma unroll
            for (int fm = 0; fm < 4; fm++) {
                const unsigned mrow = (unsigned)(wm + fm * 16 + (lane & 7) + ((lane >> 3) & 1) * 8);
                const unsigned kb   = (unsigned)(k16 * 32 + ((lane >> 4) & 1) * 16);
                ldm_x4(a[fm][0], a[fm][1], a[fm][2], a[fm][3],
                       abase + mrow * 128u + (kb ^ lpat));
            }
#pragma unroll
            for (int p = 0; p < 2; p++) {
                const unsigned grp  = (unsigned)(lane >> 3);
                const unsigned nrow = (unsigned)(wn + p * 16 + (lane & 7)) + (grp >> 1) * 8u;
                const unsigned kb   = (unsigned)k16 * 32u + (grp & 1) * 16u;
                unsigned r0, r1, r2, r3;
                ldm_x4(r0, r1, r2, r3, bbase + nrow * 128u + (kb ^ lpat));
                b[p * 2][0] = r0;  b[p * 2][1] = r1;
                b[p * 2 + 1][0] = r2;  b[p * 2 + 1][1] = r3;
            }
#pragma unroll
            for (int fm = 0; fm < 4; fm++)
#pragma unroll
                for (int fn = 0; fn < 4; fn++) {
                    if (FP16) mma_fp16(acc[fm][fn], a[fm], b[fn]);
                    else      mma_bf16(acc[fm][fn], a[fm], b[fn]);
                }
        }
        __syncthreads();
        if (st + 2 < T) load_st(st + 2);
    }

    // ---- epilogue: acc[fm][fn] is m16n8 at (wm+fm*16, wn+fn*8) ----
    const int g  = lane >> 2;
    const int tc = lane & 3;
#pragma unroll
    for (int fm = 0; fm < 4; fm++) {
        const int r0 = m0 + wm + fm * 16 + g;
        const int r1 = r0 + 8;
        float b0 = 0.f, b1 = 0.f;
        if (EPI == 1 || EPI == 5) { b0 = bias[r0]; b1 = bias[r1]; }
#pragma unroll
        for (int fn = 0; fn < 4; fn++) {
            const int col = n0 + wn + fn * 8 + tc * 2;
            float v00 = acc[fm][fn][0], v01 = acc[fm][fn][1];
            float v10 = acc[fm][fn][2], v11 = acc[fm][fn][3];
            if (EPI == 0) { v00 *= alpha; v01 *= alpha; v10 *= alpha; v11 *= alpha; }
            if (EPI == 1 || EPI == 5) { v00 += b0; v01 += b0; v10 += b1; v11 += b1; }
            if (EPI == 2) {
                const float bc0 = bias[col], bc1 = bias[col + 1];
                v00 += bc0; v01 += bc1; v10 += bc0; v11 += bc1;
            }
            if (EPI == 0 || EPI == 1) {
                float* o0 = Cf + (size_t)bz * sC + (size_t)r0 * N + col;
                float* o1 = Cf + (size_t)bz * sC + (size_t)r1 * N + col;
                *(float2*)o0 = make_float2(v00, v01);
                *(float2*)o1 = make_float2(v10, v11);
            } else if (EPI == 5) {
                __half* c0 = (__half*)Ch + (size_t)bz * sC + (size_t)r0 * N + col;
                __half* c1 = (__half*)Ch + (size_t)bz * sC + (size_t)r1 * N + col;
                *(__half2*)c0 = __floats2half2_rn(v00, v01);
                *(__half2*)c1 = __floats2half2_rn(v10, v11);
            } else {
                __nv_bfloat16 h00 = __float2bfloat16(v00), h01 = __float2bfloat16(v01);
                __nv_bfloat16 h10 = __float2bfloat16(v10), h11 = __float2bfloat16(v11);
                __nv_bfloat162 hh0; hh0.x = h00; hh0.y = h01;
                __nv_bfloat162 hh1; hh1.x = h10; hh1.y = h11;
                __nv_bfloat162 ll0, ll1;
                ll0.x = __float2bfloat16(v00 - __bfloat162float(h00));
                ll0.y = __float2bfloat16(v01 - __bfloat162float(h01));
                ll1.x = __float2bfloat16(v10 - __bfloat162float(h10));
                ll1.y = __float2bfloat16(v11 - __bfloat162float(h11));
                __nv_bfloat16* c0 = Ch + (size_t)bz * sC + (size_t)r0 * N + col;
                __nv_bfloat16* c1 = Ch + (size_t)bz * sC + (size_t)r1 * N + col;
                __nv_bfloat16* d0 = Cl + (size_t)bz * sC + (size_t)r0 * N + col;
                __nv_bfloat16* d1 = Cl + (size_t)bz * sC + (size_t)r1 * N + col;
                *(__nv_bfloat162*)c0 = hh0;
                *(__nv_bfloat162*)c1 = hh1;
                *(__nv_bfloat162*)d0 = ll0;
                *(__nv_bfloat162*)d1 = ll1;
            }
        }
    }
}

// ---------------- transpose + split: x[b][c][n] f32 -> xT hi/lo [b][n][c] ----------------
__global__ __launch_bounds__(256)
void xT_split(const float* __restrict__ x, __nv_bfloat16* __restrict__ th,
              __nv_bfloat16* __restrict__ tl)
{
    __shared__ float t[32][33];
    const int b = blockIdx.z;
    const int n0 = blockIdx.x * 32, c0 = blockIdx.y * 32;
    const int tx = threadIdx.x, ty = threadIdx.y;    // (32, 8)
    const float* xb = x + (size_t)b * CIN * NPIX;
#pragma unroll
    for (int j = 0; j < 4; j++)
        t[ty + j * 8][tx] = xb[(size_t)(c0 + ty + j * 8) * NPIX + n0 + tx];
    __syncthreads();
#pragma unroll
    for (int j = 0; j < 4; j++) {
        float v = t[tx][ty + j * 8];
        __nv_bfloat16 hh = __float2bfloat16(v);
        size_t o = ((size_t)b * NPIX + n0 + ty + j * 8) * CIN + c0 + tx;
        th[o] = hh;
        tl[o] = __float2bfloat16(v - __bfloat162float(hh));
    }
}

// ---------------- elementwise split (weights) ----------------
__global__ __launch_bounds__(256)
void split_f32(const float* __restrict__ s, __nv_bfloat16* __restrict__ h,
               __nv_bfloat16* __restrict__ l, int n)
{
    int i = blockIdx.x * 256 + threadIdx.x;
    if (i < n) {
        float v = s[i];
        __nv_bfloat16 hh = __float2bfloat16(v);
        h[i] = hh;
        l[i] = __float2bfloat16(v - __bfloat162float(hh));
    }
}

// ---------------- softmax over contiguous NPIX -> fp16 P ----------------
__global__ __launch_bounds__(256)
void softmax_half(const float* __restrict__ T, __half* __restrict__ Ph)
{
    const float* row = T + (size_t)blockIdx.x * NPIX;
    const int tid = threadIdx.x, lane = tid & 31, wid = tid >> 5;

    float v[16];
    float m = -CUDART_INF_F;
#pragma unroll
    for (int t = 0; t < 16; t++) { v[t] = row[tid + t * 256]; m = fmaxf(m, v[t]); }
#pragma unroll
    for (int o = 16; o > 0; o >>= 1) m = fmaxf(m, __shfl_xor_sync(0xffffffffu, m, o));

    __shared__ float rmax[8], rsum[8];
    if (lane == 0) rmax[wid] = m;
    __syncthreads();
#pragma unroll
    for (int w = 0; w < 8; w++) m = fmaxf(m, rmax[w]);

    float s = 0.f;
#pragma unroll
    for (int t = 0; t < 16; t++) { v[t] = __expf(v[t] - m); s += v[t]; }
#pragma unroll
    for (int o = 16; o > 0; o >>= 1) s += __shfl_xor_sync(0xffffffffu, s, o);
    if (lane == 0) rsum[wid] = s;
    __syncthreads();
    float tot = 0.f;
#pragma unroll
    for (int w = 0; w < 8; w++) tot += rsum[w];
    const float inv = 1.f / tot;

    __half* prow = Ph + (size_t)blockIdx.x * NPIX;
#pragma unroll
    for (int t = 0; t < 16; t += 2) {
        __half2 h2 = __floats2half2_rn(v[t] * inv, 0.f);
        // write two independent elements (stride 256 apart) as scalars
        prow[tid + t * 256]       = __low2half(__floats2half2_rn(v[t] * inv, 0.f));
        prow[tid + (t + 1) * 256] = __low2half(__floats2half2_rn(v[t + 1] * inv, 0.f));
        (void)h2;
    }
}

// ---------------- launch ----------------
extern "C" void kernel_launch(void* const* d_in, const int* in_sizes, int n_in,
                              void* d_out, int out_size)
{
    (void)in_sizes; (void)n_in; (void)out_size;
    const float* x  = (const float*)d_in[0];
    const float* Wq = (const float*)d_in[1];
    const float* bq = (const float*)d_in[2];
    const float* Wk = (const float*)d_in[3];
    const float* bk = (const float*)d_in[4];
    const float* Wv = (const float*)d_in[5];
    const float* bv = (const float*)d_in[6];
    const float* Wo = (const float*)d_in[7];
    const float* bo = (const float*)d_in[8];
    float* out = (float*)d_out;

    __nv_bfloat16 *xh, *xl, *wh, *wl, *qh, *ql, *kh, *kl, *rh, *rl;
    __half *vh, *Ph;
    float* Tf;
    cudaGetSymbolAddress((void**)&xh, g_xT_hi);  cudaGetSymbolAddress((void**)&xl, g_xT_lo);
    cudaGetSymbolAddress((void**)&wh, g_w_hi);   cudaGetSymbolAddress((void**)&wl, g_w_lo);
    cudaGetSymbolAddress((void**)&qh, g_q_hi);   cudaGetSymbolAddress((void**)&ql, g_q_lo);
    cudaGetSymbolAddress((void**)&kh, g_k_hi);   cudaGetSymbolAddress((void**)&kl, g_k_lo);
    cudaGetSymbolAddress((void**)&vh, g_v_h);
    cudaGetSymbolAddress((void**)&Tf, g_T);
    cudaGetSymbolAddress((void**)&Ph, g_P_h);
    cudaGetSymbolAddress((void**)&rh, g_r_hi);   cudaGetSymbolAddress((void**)&rl, g_r_lo);

    cudaFuncSetAttribute(tc_gemm<0,3,false>, cudaFuncAttributeMaxDynamicSharedMemorySize, SMEM_GEMM_BYTES);
    cudaFuncSetAttribute(tc_gemm<1,3,false>, cudaFuncAttributeMaxDynamicSharedMemorySize, SMEM_GEMM_BYTES);
    cudaFuncSetAttribute(tc_gemm<2,3,false>, cudaFuncAttributeMaxDynamicSharedMemorySize, SMEM_GEMM_BYTES);
    cudaFuncSetAttribute(tc_gemm<5,3,false>, cudaFuncAttributeMaxDynamicSharedMemorySize, SMEM_GEMM_BYTES);
    cudaFuncSetAttribute(tc_gemm<4,1,true>,  cudaFuncAttributeMaxDynamicSharedMemorySize, SMEM_GEMM_BYTES);

    const size_t sX = (size_t)NPIX * CIN;   // x^T per-batch stride (elems)
    const size_t sQ = (size_t)NPIX * LAT;   // q^T / k^T / r per-batch stride
    const size_t sV = (size_t)LAT * NPIX;   // v per-batch stride
    const size_t sT = (size_t)NPIX * NPIX;  // logits / P per-batch stride
    const int    WN = LAT * CIN;            // 65536

    // 0) conversions
    xT_split<<<dim3(NPIX / 32, CIN / 32, B_), dim3(32, 8)>>>(x, xh, xl);
    split_f32<<<WN / 256, 256>>>(Wq, wh + 0 * WN, wl + 0 * WN, WN);
    split_f32<<<WN / 256, 256>>>(Wk, wh + 1 * WN, wl + 1 * WN, WN);
    split_f32<<<WN / 256, 256>>>(Wv, wh + 2 * WN, wl + 2 * WN, WN);
    split_f32<<<WN / 256, 256>>>(Wo, wh + 3 * WN, wl + 3 * WN, WN);

    // 1) q^T[n,l] = sum_c xT[n,c]*Wq[l,c] + bq[l]   (bf16 3-seg, split out, bias col)
    tc_gemm<2,3,false><<<dim3(LAT / 128, NPIX / 128, B_), 256, SMEM_GEMM_BYTES>>>(
        xh, xl, sX, wh + 0 * WN, wl + 0 * WN, 0, nullptr, qh, ql, sQ, bq, LAT, CIN, 1.f);
    tc_gemm<2,3,false><<<dim3(LAT / 128, NPIX / 128, B_), 256, SMEM_GEMM_BYTES>>>(
        xh, xl, sX, wh + 1 * WN, wl + 1 * WN, 0, nullptr, kh, kl, sQ, bk, LAT, CIN, 1.f);
    // v[l,n] = sum_c Wv[l,c]*xT[n,c] + bv[l]        (bf16 3-seg, fp16 out, bias row)
    tc_gemm<5,3,false><<<dim3(NPIX / 128, LAT / 128, B_), 256, SMEM_GEMM_BYTES>>>(
        wh + 2 * WN, wl + 2 * WN, 0, xh, xl, sX, nullptr, (__nv_bfloat16*)vh, nullptr,
        sV, bv, NPIX, CIN, 1.f);

    // 2) T[j,i] = (sum_c kT[j,c]*qT[i,c]) / 16      (bf16 3-seg, f32 * alpha)
    tc_gemm<0,3,false><<<dim3(NPIX / 128, NPIX / 128, B_), 256, SMEM_GEMM_BYTES>>>(
        kh, kl, sQ, qh, ql, sQ, Tf, nullptr, nullptr, sT, nullptr, NPIX, LAT, 1.f / 16.f);

    // 3) softmax over i (contiguous) per (b, j) row; emit fp16 P
    softmax_half<<<B_ * NPIX, 256>>>(Tf, Ph);

    // 4) r[j,c] = sum_i P[j,i]*v[c,i]               (fp16 single-seg, split out)
    tc_gemm<4,1,true><<<dim3(LAT / 128, NPIX / 128, B_), 256, SMEM_GEMM_BYTES>>>(
        (const __nv_bfloat16*)Ph, nullptr, sT, (const __nv_bfloat16*)vh, nullptr, sV,
        nullptr, rh, rl, sQ, nullptr, LAT, NPIX, 1.f);

    // 5) out[o,j] = sum_c Wo[o,c]*r[j,c] + bo[o]    (bf16 3-seg, f32 + bias row)
    tc_gemm<1,3,false><<<dim3(NPIX / 128, CIN / 128, B_), 256, SMEM_GEMM_BYTES>>>(
        wh + 3 * WN, wl + 3 * WN, 0, rh, rl, sQ, out, nullptr, nullptr,
        (size_t)CIN * NPIX, bo, NPIX, LAT, 1.f);
}

// round 10
// speedup vs baseline: 2.8765x; 1.4761x over previous
#include <cuda_runtime.h>
#include <cuda_bf16.h>
#include <cuda_fp16.h>
#include <math_constants.h>

#define B_   4
#define CIN  256
#define LAT  256
#define NPIX 4096   // 64*64

// ---------------- scratch (__device__ globals; no allocs allowed) ----------------
__device__ __align__(16) __nv_bfloat16 g_xT_hi[B_ * NPIX * CIN];   // x^T  [b][n][c]
__device__ __align__(16) __nv_bfloat16 g_xT_lo[B_ * NPIX * CIN];
__device__ __align__(16) __nv_bfloat16 g_w_hi[4 * LAT * CIN];      // Wq,Wk,Wv,Wo
__device__ __align__(16) __nv_bfloat16 g_w_lo[4 * LAT * CIN];
__device__ __align__(16) __half        g_q_h[B_ * NPIX * LAT];     // q^T fp16 [b][n][l]
__device__ __align__(16) __half        g_k_h[B_ * NPIX * LAT];     // k^T fp16
__device__ __align__(16) __half        g_v_h[B_ * LAT * NPIX];     // v fp16 [b][l][n]
__device__ __align__(16) float         g_T[(size_t)B_ * NPIX * NPIX];   // logits [b][j][i] f32
__device__ __align__(16) __half        g_P_h[(size_t)B_ * NPIX * NPIX]; // P fp16 [b][j][i]
__device__ __align__(16) __nv_bfloat16 g_r_hi[B_ * NPIX * LAT];    // r [b][j][c]
__device__ __align__(16) __nv_bfloat16 g_r_lo[B_ * NPIX * LAT];

// ---------------- helpers ----------------
__device__ __forceinline__ unsigned s2u(const void* p) {
    unsigned a;
    asm("{ .reg .u64 t; cvta.to.shared.u64 t, %1; cvt.u32.u64 %0, t; }" : "=r"(a) : "l"(p));
    return a;
}
__device__ __forceinline__ void cp16(unsigned s, const void* g) {
    asm volatile("cp.async.cg.shared.global [%0], [%1], 16;" :: "r"(s), "l"(g));
}
#define CP_COMMIT() asm volatile("cp.async.commit_group;" ::: "memory")
#define CP_WAIT1()  asm volatile("cp.async.wait_group 1;" ::: "memory")
#define CP_WAIT0()  asm volatile("cp.async.wait_group 0;" ::: "memory")

__device__ __forceinline__ void ldm_x4(unsigned& r0, unsigned& r1, unsigned& r2, unsigned& r3,
                                       unsigned addr) {
    asm volatile("ldmatrix.sync.aligned.m8n8.x4.shared.b16 {%0,%1,%2,%3}, [%4];"
                 : "=r"(r0), "=r"(r1), "=r"(r2), "=r"(r3) : "r"(addr));
}
__device__ __forceinline__ void mma_bf16(float* c, const unsigned* a, const unsigned* b) {
    asm volatile(
        "mma.sync.aligned.m16n8k16.row.col.f32.bf16.bf16.f32 "
        "{%0,%1,%2,%3}, {%4,%5,%6,%7}, {%8,%9}, {%0,%1,%2,%3};"
        : "+f"(c[0]), "+f"(c[1]), "+f"(c[2]), "+f"(c[3])
        : "r"(a[0]), "r"(a[1]), "r"(a[2]), "r"(a[3]), "r"(b[0]), "r"(b[1]));
}
__device__ __forceinline__ void mma_fp16(float* c, const unsigned* a, const unsigned* b) {
    asm volatile(
        "mma.sync.aligned.m16n8k16.row.col.f32.f16.f16.f32 "
        "{%0,%1,%2,%3}, {%4,%5,%6,%7}, {%8,%9}, {%0,%1,%2,%3};"
        : "+f"(c[0]), "+f"(c[1]), "+f"(c[2]), "+f"(c[3])
        : "r"(a[0]), "r"(a[1]), "r"(a[2]), "r"(a[3]), "r"(b[0]), "r"(b[1]));
}

// ---------------- HMMA GEMM: D[m,n] = sum_k A[m,k]*B[n,k] ----------------
// 16-bit element arrays (bf16 or fp16), K-major.
// NSEG==3: hi/lo bf16 split, accumulates hi*hi + lo*hi + hi*lo.
// NSEG==1: single-segment (A_lo/B_lo unused).
// EPI: 0 = f32 * alpha          (logits)
//      1 = f32 + bias[row]      (final out)
//      4 = split, no bias       (r)
//      5 = fp16 + bias[row]     (v projection)
//      6 = fp16 + bias[col]     (q, k projections)
// CTA tile 128x128, BK=64, 8 warps (2x4), warp tile 64x32.
#define SMEM_GEMM_BYTES 65536
template<int EPI, int NSEG, bool FP16>
__global__ __launch_bounds__(256, 2)
void tc_gemm(const __nv_bfloat16* __restrict__ A_hi, const __nv_bfloat16* __restrict__ A_lo, size_t sA,
             const __nv_bfloat16* __restrict__ B_hi, const __nv_bfloat16* __restrict__ B_lo, size_t sB,
             float* __restrict__ Cf, __nv_bfloat16* __restrict__ Ch, __nv_bfloat16* __restrict__ Cl,
             size_t sC, const float* __restrict__ bias, int N, int K, float alpha)
{
    extern __shared__ char smem[];
    const unsigned sbase = s2u(smem);
    const int tid  = threadIdx.x;
    const int warp = tid >> 5, lane = tid & 31;
    const int wm   = (warp >> 2) * 64;      // warp m offset in CTA tile
    const int wn   = (warp & 3) * 32;       // warp n offset
    const int m0   = blockIdx.y * 128, n0 = blockIdx.x * 128, bz = blockIdx.z;

    A_hi += (size_t)bz * sA;  B_hi += (size_t)bz * sB;
    if (NSEG == 3) { A_lo += (size_t)bz * sA;  B_lo += (size_t)bz * sB; }

    const int KC = K >> 6;       // 64-wide K chunks per segment
    const int T  = NSEG * KC;

    auto load_st = [&](int st) {
        const int buf = st & 1;
        const int seg = (NSEG == 3) ? (st / KC) : 0;
        const int kc  = st - seg * KC;
        const int r   = tid & 127;
        const __nv_bfloat16* src;
        unsigned sa;
        if (tid < 128) {
            src = ((NSEG == 3 && seg == 1) ? A_lo : A_hi) + (size_t)(m0 + r) * K + (kc << 6);
            sa  = sbase + buf * 32768u;
        } else {
            src = ((NSEG == 3 && seg == 2) ? B_lo : B_hi) + (size_t)(n0 + r) * K + (kc << 6);
            sa  = sbase + buf * 32768u + 16384u;
        }
        const unsigned pat  = (unsigned)(r & 7) << 4;
        const unsigned base = sa + (unsigned)r * 128u;
#pragma unroll
        for (int c = 0; c < 8; c++)
            cp16(base + (((unsigned)c * 16u) ^ pat), src + c * 8);
        CP_COMMIT();
    };

    float acc[4][4][4];
#pragma unroll
    for (int i = 0; i < 4; i++)
#pragma unroll
        for (int j = 0; j < 4; j++)
#pragma unroll
            for (int e = 0; e < 4; e++) acc[i][j][e] = 0.f;

    load_st(0);
    load_st(1);

    const unsigned lpat = (unsigned)(lane & 7) << 4;

    for (int st = 0; st < T; st++) {
        if (st + 1 < T) CP_WAIT1(); else CP_WAIT0();
        __syncthreads();

        const unsigned abase = sbase + (unsigned)(st & 1) * 32768u;
        const unsigned bbase = abase + 16384u;

#pragma unroll
        for (int k16 = 0; k16 < 4; k16++) {
            unsigned a[4][4], b[4][2];
#pragma unroll
            for (int fm = 0; fm < 4; fm++) {
                const unsigned mrow = (unsigned)(wm + fm * 16 + (lane & 7) + ((lane >> 3) & 1) * 8);
                const unsigned kb   = (unsigned)(k16 * 32 + ((lane >> 4) & 1) * 16);
                ldm_x4(a[fm][0], a[fm][1], a[fm][2], a[fm][3],
                       abase + mrow * 128u + (kb ^ lpat));
            }
#pragma unroll
            for (int p = 0; p < 2; p++) {
                const unsigned grp  = (unsigned)(lane >> 3);
                const unsigned nrow = (unsigned)(wn + p * 16 + (lane & 7)) + (grp >> 1) * 8u;
                const unsigned kb   = (unsigned)k16 * 32u + (grp & 1) * 16u;
                unsigned r0, r1, r2, r3;
                ldm_x4(r0, r1, r2, r3, bbase + nrow * 128u + (kb ^ lpat));
                b[p * 2][0] = r0;  b[p * 2][1] = r1;
                b[p * 2 + 1][0] = r2;  b[p * 2 + 1][1] = r3;
            }
#pragma unroll
            for (int fm = 0; fm < 4; fm++)
#pragma unroll
                for (int fn = 0; fn < 4; fn++) {
                    if (FP16) mma_fp16(acc[fm][fn], a[fm], b[fn]);
                    else      mma_bf16(acc[fm][fn], a[fm], b[fn]);
                }
        }
        __syncthreads();
        if (st + 2 < T) load_st(st + 2);
    }

    // ---- epilogue: acc[fm][fn] is m16n8 at (wm+fm*16, wn+fn*8) ----
    const int g  = lane >> 2;
    const int tc = lane & 3;
#pragma unroll
    for (int fm = 0; fm < 4; fm++) {
        const int r0 = m0 + wm + fm * 16 + g;
        const int r1 = r0 + 8;
        float b0 = 0.f, b1 = 0.f;
        if (EPI == 1 || EPI == 5) { b0 = bias[r0]; b1 = bias[r1]; }
#pragma unroll
        for (int fn = 0; fn < 4; fn++) {
            const int col = n0 + wn + fn * 8 + tc * 2;
            float v00 = acc[fm][fn][0], v01 = acc[fm][fn][1];
            float v10 = acc[fm][fn][2], v11 = acc[fm][fn][3];
            if (EPI == 0) { v00 *= alpha; v01 *= alpha; v10 *= alpha; v11 *= alpha; }
            if (EPI == 1 || EPI == 5) { v00 += b0; v01 += b0; v10 += b1; v11 += b1; }
            if (EPI == 6) {
                const float bc0 = bias[col], bc1 = bias[col + 1];
                v00 += bc0; v01 += bc1; v10 += bc0; v11 += bc1;
            }
            if (EPI == 0 || EPI == 1) {
                float* o0 = Cf + (size_t)bz * sC + (size_t)r0 * N + col;
                float* o1 = Cf + (size_t)bz * sC + (size_t)r1 * N + col;
                *(float2*)o0 = make_float2(v00, v01);
                *(float2*)o1 = make_float2(v10, v11);
            } else if (EPI == 5 || EPI == 6) {
                __half* c0 = (__half*)Ch + (size_t)bz * sC + (size_t)r0 * N + col;
                __half* c1 = (__half*)Ch + (size_t)bz * sC + (size_t)r1 * N + col;
                *(__half2*)c0 = __floats2half2_rn(v00, v01);
                *(__half2*)c1 = __floats2half2_rn(v10, v11);
            } else {
                __nv_bfloat16 h00 = __float2bfloat16(v00), h01 = __float2bfloat16(v01);
                __nv_bfloat16 h10 = __float2bfloat16(v10), h11 = __float2bfloat16(v11);
                __nv_bfloat162 hh0; hh0.x = h00; hh0.y = h01;
                __nv_bfloat162 hh1; hh1.x = h10; hh1.y = h11;
                __nv_bfloat162 ll0, ll1;
                ll0.x = __float2bfloat16(v00 - __bfloat162float(h00));
                ll0.y = __float2bfloat16(v01 - __bfloat162float(h01));
                ll1.x = __float2bfloat16(v10 - __bfloat162float(h10));
                ll1.y = __float2bfloat16(v11 - __bfloat162float(h11));
                __nv_bfloat16* c0 = Ch + (size_t)bz * sC + (size_t)r0 * N + col;
                __nv_bfloat16* c1 = Ch + (size_t)bz * sC + (size_t)r1 * N + col;
                __nv_bfloat16* d0 = Cl + (size_t)bz * sC + (size_t)r0 * N + col;
                __nv_bfloat16* d1 = Cl + (size_t)bz * sC + (size_t)r1 * N + col;
                *(__nv_bfloat162*)c0 = hh0;
                *(__nv_bfloat162*)c1 = hh1;
                *(__nv_bfloat162*)d0 = ll0;
                *(__nv_bfloat162*)d1 = ll1;
            }
        }
    }
}

// ---------------- transpose + split: x[b][c][n] f32 -> xT hi/lo [b][n][c] ----------------
__global__ __launch_bounds__(256)
void xT_split(const float* __restrict__ x, __nv_bfloat16* __restrict__ th,
              __nv_bfloat16* __restrict__ tl)
{
    __shared__ float t[32][33];
    const int b = blockIdx.z;
    const int n0 = blockIdx.x * 32, c0 = blockIdx.y * 32;
    const int tx = threadIdx.x, ty = threadIdx.y;    // (32, 8)
    const float* xb = x + (size_t)b * CIN * NPIX;
#pragma unroll
    for (int j = 0; j < 4; j++)
        t[ty + j * 8][tx] = xb[(size_t)(c0 + ty + j * 8) * NPIX + n0 + tx];
    __syncthreads();
#pragma unroll
    for (int j = 0; j < 4; j++) {
        float v = t[tx][ty + j * 8];
        __nv_bfloat16 hh = __float2bfloat16(v);
        size_t o = ((size_t)b * NPIX + n0 + ty + j * 8) * CIN + c0 + tx;
        th[o] = hh;
        tl[o] = __float2bfloat16(v - __bfloat162float(hh));
    }
}

// ---------------- elementwise split (weights) ----------------
__global__ __launch_bounds__(256)
void split_f32(const float* __restrict__ s, __nv_bfloat16* __restrict__ h,
               __nv_bfloat16* __restrict__ l, int n)
{
    int i = blockIdx.x * 256 + threadIdx.x;
    if (i < n) {
        float v = s[i];
        __nv_bfloat16 hh = __float2bfloat16(v);
        h[i] = hh;
        l[i] = __float2bfloat16(v - __bfloat162float(hh));
    }
}

// ---------------- softmax over contiguous NPIX -> fp16 P ----------------
__global__ __launch_bounds__(256)
void softmax_half(const float* __restrict__ T, __half* __restrict__ Ph)
{
    const float* row = T + (size_t)blockIdx.x * NPIX;
    const int tid = threadIdx.x, lane = tid & 31, wid = tid >> 5;

    float v[16];
    float m = -CUDART_INF_F;
#pragma unroll
    for (int t = 0; t < 16; t++) { v[t] = row[tid + t * 256]; m = fmaxf(m, v[t]); }
#pragma unroll
    for (int o = 16; o > 0; o >>= 1) m = fmaxf(m, __shfl_xor_sync(0xffffffffu, m, o));

    __shared__ float rmax[8], rsum[8];
    if (lane == 0) rmax[wid] = m;
    __syncthreads();
#pragma unroll
    for (int w = 0; w < 8; w++) m = fmaxf(m, rmax[w]);

    float s = 0.f;
#pragma unroll
    for (int t = 0; t < 16; t++) { v[t] = __expf(v[t] - m); s += v[t]; }
#pragma unroll
    for (int o = 16; o > 0; o >>= 1) s += __shfl_xor_sync(0xffffffffu, s, o);
    if (lane == 0) rsum[wid] = s;
    __syncthreads();
    float tot = 0.f;
#pragma unroll
    for (int w = 0; w < 8; w++) tot += rsum[w];
    const float inv = 1.f / tot;

    __half* prow = Ph + (size_t)blockIdx.x * NPIX;
#pragma unroll
    for (int t = 0; t < 16; t++)
        prow[tid + t * 256] = __float2half_rn(v[t] * inv);
}

// ---------------- launch ----------------
extern "C" void kernel_launch(void* const* d_in, const int* in_sizes, int n_in,
                              void* d_out, int out_size)
{
    (void)in_sizes; (void)n_in; (void)out_size;
    const float* x  = (const float*)d_in[0];
    const float* Wq = (const float*)d_in[1];
    const float* bq = (const float*)d_in[2];
    const float* Wk = (const float*)d_in[3];
    const float* bk = (const float*)d_in[4];
    const float* Wv = (const float*)d_in[5];
    const float* bv = (const float*)d_in[6];
    const float* Wo = (const float*)d_in[7];
    const float* bo = (const float*)d_in[8];
    float* out = (float*)d_out;

    __nv_bfloat16 *xh, *xl, *wh, *wl, *rh, *rl;
    __half *qh, *kh, *vh, *Ph;
    float* Tf;
    cudaGetSymbolAddress((void**)&xh, g_xT_hi);  cudaGetSymbolAddress((void**)&xl, g_xT_lo);
    cudaGetSymbolAddress((void**)&wh, g_w_hi);   cudaGetSymbolAddress((void**)&wl, g_w_lo);
    cudaGetSymbolAddress((void**)&qh, g_q_h);    cudaGetSymbolAddress((void**)&kh, g_k_h);
    cudaGetSymbolAddress((void**)&vh, g_v_h);
    cudaGetSymbolAddress((void**)&Tf, g_T);
    cudaGetSymbolAddress((void**)&Ph, g_P_h);
    cudaGetSymbolAddress((void**)&rh, g_r_hi);   cudaGetSymbolAddress((void**)&rl, g_r_lo);

    cudaFuncSetAttribute(tc_gemm<0,1,true>,  cudaFuncAttributeMaxDynamicSharedMemorySize, SMEM_GEMM_BYTES);
    cudaFuncSetAttribute(tc_gemm<1,3,false>, cudaFuncAttributeMaxDynamicSharedMemorySize, SMEM_GEMM_BYTES);
    cudaFuncSetAttribute(tc_gemm<4,1,true>,  cudaFuncAttributeMaxDynamicSharedMemorySize, SMEM_GEMM_BYTES);
    cudaFuncSetAttribute(tc_gemm<5,3,false>, cudaFuncAttributeMaxDynamicSharedMemorySize, SMEM_GEMM_BYTES);
    cudaFuncSetAttribute(tc_gemm<6,3,false>, cudaFuncAttributeMaxDynamicSharedMemorySize, SMEM_GEMM_BYTES);

    const size_t sX = (size_t)NPIX * CIN;   // x^T per-batch stride (elems)
    const size_t sQ = (size_t)NPIX * LAT;   // q^T / k^T / r per-batch stride
    const size_t sV = (size_t)LAT * NPIX;   // v per-batch stride
    const size_t sT = (size_t)NPIX * NPIX;  // logits / P per-batch stride
    const int    WN = LAT * CIN;            // 65536

    // 0) conversions
    xT_split<<<dim3(NPIX / 32, CIN / 32, B_), dim3(32, 8)>>>(x, xh, xl);
    split_f32<<<WN / 256, 256>>>(Wq, wh + 0 * WN, wl + 0 * WN, WN);
    split_f32<<<WN / 256, 256>>>(Wk, wh + 1 * WN, wl + 1 * WN, WN);
    split_f32<<<WN / 256, 256>>>(Wv, wh + 2 * WN, wl + 2 * WN, WN);
    split_f32<<<WN / 256, 256>>>(Wo, wh + 3 * WN, wl + 3 * WN, WN);

    // 1) q^T[n,l] = sum_c xT[n,c]*Wq[l,c] + bq[l]   (bf16 3-seg in, fp16 out, bias col)
    tc_gemm<6,3,false><<<dim3(LAT / 128, NPIX / 128, B_), 256, SMEM_GEMM_BYTES>>>(
        xh, xl, sX, wh + 0 * WN, wl + 0 * WN, 0, nullptr, (__nv_bfloat16*)qh, nullptr,
        sQ, bq, LAT, CIN, 1.f);
    tc_gemm<6,3,false><<<dim3(LAT / 128, NPIX / 128, B_), 256, SMEM_GEMM_BYTES>>>(
        xh, xl, sX, wh + 1 * WN, wl + 1 * WN, 0, nullptr, (__nv_bfloat16*)kh, nullptr,
        sQ, bk, LAT, CIN, 1.f);
    // v[l,n] = sum_c Wv[l,c]*xT[n,c] + bv[l]        (bf16 3-seg in, fp16 out, bias row)
    tc_gemm<5,3,false><<<dim3(NPIX / 128, LAT / 128, B_), 256, SMEM_GEMM_BYTES>>>(
        wh + 2 * WN, wl + 2 * WN, 0, xh, xl, sX, nullptr, (__nv_bfloat16*)vh, nullptr,
        sV, bv, NPIX, CIN, 1.f);

    // 2) T[j,i] = (sum_c kT[j,c]*qT[i,c]) / 16      (fp16 single-seg, f32 * alpha)
    tc_gemm<0,1,true><<<dim3(NPIX / 128, NPIX / 128, B_), 256, SMEM_GEMM_BYTES>>>(
        (const __nv_bfloat16*)kh, nullptr, sQ, (const __nv_bfloat16*)qh, nullptr, sQ,
        Tf, nullptr, nullptr, sT, nullptr, NPIX, LAT, 1.f / 16.f);

    // 3) softmax over i (contiguous) per (b, j) row; emit fp16 P
    softmax_half<<<B_ * NPIX, 256>>>(Tf, Ph);

    // 4) r[j,c] = sum_i P[j,i]*v[c,i]               (fp16 single-seg, split out)
    tc_gemm<4,1,true><<<dim3(LAT / 128, NPIX / 128, B_), 256, SMEM_GEMM_BYTES>>>(
        (const __nv_bfloat16*)Ph, nullptr, sT, (const __nv_bfloat16*)vh, nullptr, sV,
        nullptr, rh, rl, sQ, nullptr, LAT, NPIX, 1.f);

    // 5) out[o,j] = sum_c Wo[o,c]*r[j,c] + bo[o]    (bf16 3-seg, f32 + bias row)
    tc_gemm<1,3,false><<<dim3(NPIX / 128, CIN / 128, B_), 256, SMEM_GEMM_BYTES>>>(
        wh + 3 * WN, wl + 3 * WN, 0, rh, rl, sQ, out, nullptr, nullptr,
        (size_t)CIN * NPIX, bo, NPIX, LAT, 1.f);
}